// round 9
// baseline (speedup 1.0000x reference)
#include <cuda_runtime.h>
#include <cstdint>

#define CRF_B 512
#define CRF_S 1024
#define CRF_T 64
#define CHUNK 32
#define NCHUNK (CRF_S / CHUNK)
#define NWARP  (CRF_B / 2)          /* 256 CTAs, one warp each, 2 rows per warp */

__device__ float g_partial[CRF_B];
__device__ int   g_count = 0;

typedef unsigned long long u64;

__device__ __forceinline__ float ex2f(float x) {
    float r; asm("ex2.approx.f32 %0, %1;" : "=f"(r) : "f"(x)); return r;
}
__device__ __forceinline__ float lg2f(float x) {
    float r; asm("lg2.approx.f32 %0, %1;" : "=f"(r) : "f"(x)); return r;
}
__device__ __forceinline__ u64 pack2(float lo, float hi) {
    u64 r; asm("mov.b64 %0, {%1, %2};" : "=l"(r) : "f"(lo), "f"(hi)); return r;
}
__device__ __forceinline__ void unpack2(u64 v, float& lo, float& hi) {
    asm("mov.b64 {%0, %1}, %2;" : "=f"(lo), "=f"(hi) : "l"(v));
}
__device__ __forceinline__ u64 ffma2(u64 a, u64 b, u64 c) {
    u64 d; asm("fma.rn.f32x2 %0, %1, %2, %3;" : "=l"(d) : "l"(a), "l"(b), "l"(c));
    return d;
}
__device__ __forceinline__ u64 fadd2(u64 a, u64 b) {
    u64 d; asm("add.rn.f32x2 %0, %1, %2;" : "=l"(d) : "l"(a), "l"(b));
    return d;
}
__device__ __forceinline__ void cp16(uint32_t dst, const void* src) {
    asm volatile("cp.async.cg.shared.global [%0], [%1], 16;" :: "r"(dst), "l"(src));
}

__global__ __launch_bounds__(32, 1)
void crf_main(const float* __restrict__ emis,
              const int*   __restrict__ tags,
              const float* __restrict__ mask,
              const float* __restrict__ trans,
              float* __restrict__ out)
{
    const int bA = 2 * blockIdx.x;      // row A
    const int bB = bA + 1;              // row B
    const int l  = threadIdx.x;         // lane; owns columns 2l, 2l+1
    const int c0 = 2 * l;

    __shared__ __align__(16) float sEm[2][2][CHUNK][CRF_T];  // [row][buf] 32 KB
    __shared__ __align__(16) float sMk[2][2][CHUNK];
    __shared__ __align__(16) int   sTg[2][2][CHUNK];
    __shared__ __align__(16) float sE[2][2][CRF_T];          // [row][buf]

    const float LOG2E = 1.4426950408889634f;
    const float LN2   = 0.6931471805599453f;

    const float* mbA = mask + (size_t)bA * CRF_S;
    const float* mbB = mask + (size_t)bB * CRF_S;
    const int*   tbA = tags + (size_t)bA * CRF_S;
    const int*   tbB = tags + (size_t)bB * CRF_S;
    const float* eA  = emis + (size_t)bA * CRF_S * CRF_T;
    const float* eB  = emis + (size_t)bB * CRF_S * CRF_T;

    // ---- cp.async chunk issuer for both rows -------------------------------
    auto issue_chunk = [&](int c) {
        const int cb = c & 1;
        const float* sA = eA + (size_t)c * CHUNK * CRF_T;
        const float* sB = eB + (size_t)c * CHUNK * CRF_T;
        uint32_t dA = (uint32_t)__cvta_generic_to_shared(&sEm[0][cb][0][0]);
        uint32_t dB = (uint32_t)__cvta_generic_to_shared(&sEm[1][cb][0][0]);
        #pragma unroll
        for (int k = 0; k < 16; k++) {
            int u = k * 32 + l;
            cp16(dA + u * 16, sA + u * 4);
            cp16(dB + u * 16, sB + u * 4);
        }
        if (l < 8) {
            uint32_t dm = (uint32_t)__cvta_generic_to_shared(&sMk[0][cb][0]);
            cp16(dm + l * 16, mbA + c * CHUNK + l * 4);
        } else if (l < 16) {
            uint32_t dm = (uint32_t)__cvta_generic_to_shared(&sMk[1][cb][0]);
            cp16(dm + (l - 8) * 16, mbB + c * CHUNK + (l - 8) * 4);
        } else if (l < 24) {
            uint32_t dt = (uint32_t)__cvta_generic_to_shared(&sTg[0][cb][0]);
            cp16(dt + (l - 16) * 16, tbA + c * CHUNK + (l - 16) * 4);
        } else {
            uint32_t dt = (uint32_t)__cvta_generic_to_shared(&sTg[1][cb][0]);
            cp16(dt + (l - 24) * 16, tbB + c * CHUNK + (l - 24) * 4);
        }
        asm volatile("cp.async.commit_group;" ::: "memory");
    };

    issue_chunk(0);
    issue_chunk(1);

    // -------- Texp columns c0, c0+1 (shared by BOTH rows): 64 u64 regs ------
    u64 tA[CRF_T / 2], tB[CRF_T / 2];
    #pragma unroll
    for (int k = 0; k < CRF_T / 2; k++) {
        float2 r0 = *reinterpret_cast<const float2*>(trans + (2 * k)     * CRF_T + c0);
        float2 r1 = *reinterpret_cast<const float2*>(trans + (2 * k + 1) * CRF_T + c0);
        tA[k] = pack2(ex2f(r0.x * LOG2E), ex2f(r1.x * LOG2E));
        tB[k] = pack2(ex2f(r0.y * LOG2E), ex2f(r1.y * LOG2E));
    }

    // ---------------- init (step 0), both rows ----------------
    float mkA0 = mbA[0], mkB0 = mbB[0];
    float2 evA = *reinterpret_cast<const float2*>(eA + c0);
    float2 evB = *reinterpret_cast<const float2*>(eB + c0);
    float sA0 = evA.x * mkA0, sA1 = evA.y * mkA0;
    float sB0 = evB.x * mkB0, sB1 = evB.y * mkB0;

    float mrefA  = __shfl_sync(0xffffffffu, sA0, 0);
    float mrefB  = __shfl_sync(0xffffffffu, sB0, 0);
    float mrefnA = mrefA, mrefnB = mrefB;
    float prevA  = mrefA, prevB  = mrefB;

    int   tgpA = tbA[0],            tgpB = tbB[0];
    float gA   = eA[tgpA] * mkA0,   gB   = eB[tgpB] * mkB0;

    *reinterpret_cast<float2*>(&sE[0][1][c0]) =
        make_float2(ex2f((sA0 - mrefA) * LOG2E), ex2f((sA1 - mrefA) * LOG2E));
    *reinterpret_cast<float2*>(&sE[1][1][c0]) =
        make_float2(ex2f((sB0 - mrefB) * LOG2E), ex2f((sB1 - mrefB) * LOG2E));

    // ================= main recurrence (both rows per iteration) ============
    for (int c = 0; c < NCHUNK; ++c) {
        if (c >= NCHUNK - 2) asm volatile("cp.async.wait_group 0;" ::: "memory");
        else                 asm volatile("cp.async.wait_group 1;" ::: "memory");
        __syncwarp();

        const int cb   = c & 1;
        const int sBeg = (c == 0) ? 1 : c * CHUNK;
        const int sEnd = (c == NCHUNK - 1) ? (CRF_S - 1) : (c + 1) * CHUNK;

        #pragma unroll 4
        for (int s = sBeg; s < sEnd; ++s) {
            __syncwarp();

            const int idx = s & (CHUNK - 1);
            const int buf = s & 1;

            float  mpfA = prevA,  mpfB = prevB;
            float2 emA  = *reinterpret_cast<const float2*>(&sEm[0][cb][idx][c0]);
            float2 emB  = *reinterpret_cast<const float2*>(&sEm[1][cb][idx][c0]);
            float  mkA  = sMk[0][cb][idx],      mkB  = sMk[1][cb][idx];
            float  em0A = sEm[0][cb][idx][0],   em0B = sEm[1][cb][idx][0];

            // ---- interleaved gold steps (off-path) ----
            int   tgA = sTg[0][cb][idx],        tgB = sTg[1][cb][idx];
            float geA = sEm[0][cb][idx][tgA],   geB = sEm[1][cb][idx][tgB];
            float gtA = __ldg(trans + tgA * CRF_T + tgpA);
            float gtB = __ldg(trans + tgB * CRF_T + tgpB);
            gA = fmaf(gtA + geA, mkA, gA);      tgpA = tgA;
            gB = fmaf(gtB + geB, mkB, gB);      tgpB = tgB;

            // ---- rescale factors ----
            float mklA = mkA * LOG2E,  mklB = mkB * LOG2E;
            float drA  = (mrefA - mrefnA) * LOG2E;
            float drB  = (mrefB - mrefnB) * LOG2E;
            float edA0 = ex2f(fmaf(emA.x, mklA, drA));
            float edA1 = ex2f(fmaf(emA.y, mklA, drA));
            float edB0 = ex2f(fmaf(emB.x, mklB, drB));
            float edB1 = ex2f(fmaf(emB.y, mklB, drB));

            // ---- dots, interleaved across rows ----
            const ulonglong2* EA = reinterpret_cast<const ulonglong2*>(sE[0][buf]);
            const ulonglong2* EB = reinterpret_cast<const ulonglong2*>(sE[1][buf]);
            u64 aA0 = 0ull, aA1 = 0ull, bA0 = 0ull, bA1 = 0ull;
            u64 aB0 = 0ull, aB1 = 0ull, bB0 = 0ull, bB1 = 0ull;
            #pragma unroll
            for (int k = 0; k < CRF_T / 4; k++) {
                ulonglong2 vA = EA[k];
                ulonglong2 vB = EB[k];
                aA0 = ffma2(vA.x, tA[2 * k],     aA0);
                aB0 = ffma2(vB.x, tA[2 * k],     aB0);
                aA1 = ffma2(vA.y, tA[2 * k + 1], aA1);
                aB1 = ffma2(vB.y, tA[2 * k + 1], aB1);
                bA0 = ffma2(vA.x, tB[2 * k],     bA0);
                bB0 = ffma2(vB.x, tB[2 * k],     bB0);
                bA1 = ffma2(vA.y, tB[2 * k + 1], bA1);
                bB1 = ffma2(vB.y, tB[2 * k + 1], bB1);
            }
            u64 tAa = fadd2(aA0, aA1), tAb = fadd2(bA0, bA1);
            u64 tBa = fadd2(aB0, aB1), tBb = fadd2(bB0, bB1);
            float xAa, yAa, xAb, yAb, xBa, yBa, xBb, yBb;
            unpack2(tAa, xAa, yAa); unpack2(tAb, xAb, yAb);
            unpack2(tBa, xBa, yBa); unpack2(tBb, xBb, yBb);
            float PA0 = xAa + yAa, PA1 = xAb + yAb;
            float PB0 = xBa + yBa, PB1 = xBb + yBb;

            // ---- E(s+1), linear space ----
            *reinterpret_cast<float2*>(&sE[0][buf ^ 1][c0]) =
                make_float2(PA0 * edA0, PA1 * edA1);
            *reinterpret_cast<float2*>(&sE[1][buf ^ 1][c0]) =
                make_float2(PB0 * edB0, PB1 * edB1);

            // ---- reference scores, all lanes, branch-free ----
            float PA0b = __shfl_sync(0xffffffffu, PA0, 0);
            float PB0b = __shfl_sync(0xffffffffu, PB0, 0);
            prevA = fmaf(lg2f(PA0b), LN2, mrefA) + em0A * mkA;
            prevB = fmaf(lg2f(PB0b), LN2, mrefB) + em0B * mkB;

            mrefA = mrefnA;  mrefnA = mpfA;
            mrefB = mrefnB;  mrefnB = mpfB;
        }

        if (c + 2 < NCHUNK) issue_chunk(c + 2);
    }

    // ---------------- peeled last step (s = S-1), both rows ----------------
    {
        const int s   = CRF_S - 1;
        const int cb  = (NCHUNK - 1) & 1;
        const int idx = s & (CHUNK - 1);
        const int buf = s & 1;

        float2 emA = *reinterpret_cast<const float2*>(&sEm[0][cb][idx][c0]);
        float2 emB = *reinterpret_cast<const float2*>(&sEm[1][cb][idx][c0]);
        float  mkA = sMk[0][cb][idx],  mkB = sMk[1][cb][idx];

        int   tgA = sTg[0][cb][idx],        tgB = sTg[1][cb][idx];
        float geA = sEm[0][cb][idx][tgA],   geB = sEm[1][cb][idx][tgB];
        gA = fmaf(__ldg(trans + tgA * CRF_T + tgpA) + geA, mkA, gA);
        gB = fmaf(__ldg(trans + tgB * CRF_T + tgpB) + geB, mkB, gB);

        __syncwarp();

        const ulonglong2* EA = reinterpret_cast<const ulonglong2*>(sE[0][buf]);
        const ulonglong2* EB = reinterpret_cast<const ulonglong2*>(sE[1][buf]);
        u64 aA0 = 0ull, aA1 = 0ull, bA0 = 0ull, bA1 = 0ull;
        u64 aB0 = 0ull, aB1 = 0ull, bB0 = 0ull, bB1 = 0ull;
        #pragma unroll
        for (int k = 0; k < CRF_T / 4; k++) {
            ulonglong2 vA = EA[k];
            ulonglong2 vB = EB[k];
            aA0 = ffma2(vA.x, tA[2 * k],     aA0);
            aB0 = ffma2(vB.x, tA[2 * k],     aB0);
            aA1 = ffma2(vA.y, tA[2 * k + 1], aA1);
            aB1 = ffma2(vB.y, tA[2 * k + 1], aB1);
            bA0 = ffma2(vA.x, tB[2 * k],     bA0);
            bB0 = ffma2(vB.x, tB[2 * k],     bB0);
            bA1 = ffma2(vA.y, tB[2 * k + 1], bA1);
            bB1 = ffma2(vB.y, tB[2 * k + 1], bB1);
        }
        u64 tAa = fadd2(aA0, aA1), tAb = fadd2(bA0, bA1);
        u64 tBa = fadd2(aB0, aB1), tBb = fadd2(bB0, bB1);
        float xAa, yAa, xAb, yAb, xBa, yBa, xBb, yBb;
        unpack2(tAa, xAa, yAa); unpack2(tAb, xAb, yAb);
        unpack2(tBa, xBa, yBa); unpack2(tBb, xBb, yBb);

        float scA0 = fmaf(lg2f(xAa + yAa), LN2, mrefA) + emA.x * mkA;
        float scA1 = fmaf(lg2f(xAb + yAb), LN2, mrefA) + emA.y * mkA;
        float scB0 = fmaf(lg2f(xBa + yBa), LN2, mrefB) + emB.x * mkB;
        float scB1 = fmaf(lg2f(xBb + yBb), LN2, mrefB) + emB.y * mkB;

        // final logsumexp, row A then row B (interleaved shfl chains)
        float mA = fmaxf(scA0, scA1);
        float mB = fmaxf(scB0, scB1);
        #pragma unroll
        for (int off = 16; off; off >>= 1) {
            mA = fmaxf(mA, __shfl_xor_sync(0xffffffffu, mA, off));
            mB = fmaxf(mB, __shfl_xor_sync(0xffffffffu, mB, off));
        }
        float eAe = ex2f((scA0 - mA) * LOG2E) + ex2f((scA1 - mA) * LOG2E);
        float eBe = ex2f((scB0 - mB) * LOG2E) + ex2f((scB1 - mB) * LOG2E);
        #pragma unroll
        for (int off = 16; off; off >>= 1) {
            eAe += __shfl_xor_sync(0xffffffffu, eAe, off);
            eBe += __shfl_xor_sync(0xffffffffu, eBe, off);
        }

        if (l == 0) {
            g_partial[bA] = fmaf(lg2f(eAe), LN2, mA) - gA;
            g_partial[bB] = fmaf(lg2f(eBe), LN2, mB) - gB;
        }
    }

    // ---------------- last-arriving block reduces the mean -------------------
    bool last = false;
    if (l == 0) {
        __threadfence();
        int c = atomicAdd(&g_count, 1);
        last = (c == NWARP - 1);
        if (last) g_count = 0;              // reset for graph replay
    }
    last = __shfl_sync(0xffffffffu, last, 0);
    if (last) {
        __threadfence();
        float v = 0.f;
        #pragma unroll
        for (int i = 0; i < CRF_B / 32; i++)
            v += g_partial[i * 32 + l];
        #pragma unroll
        for (int off = 16; off; off >>= 1)
            v += __shfl_xor_sync(0xffffffffu, v, off);
        if (l == 0) out[0] = v * (1.0f / CRF_B);
    }
}

extern "C" void kernel_launch(void* const* d_in, const int* in_sizes, int n_in,
                              void* d_out, int out_size)
{
    const float* emis  = (const float*)d_in[0];
    const int*   tags  = (const int*)  d_in[1];
    const float* mask  = (const float*)d_in[2];
    const float* trans = (const float*)d_in[3];

    crf_main<<<NWARP, 32>>>(emis, tags, mask, trans, (float*)d_out);
}

// round 10
// speedup vs baseline: 1.7576x; 1.7576x over previous
#include <cuda_runtime.h>
#include <cstdint>

#define CRF_B 512
#define CRF_S 1024
#define CRF_T 64
#define CHUNK 16
#define NCHUNK (CRF_S / CHUNK)     /* 64 */
#define RPC 4                       /* rows (warps) per CTA */
#define NCTA (CRF_B / RPC)          /* 128 */

__device__ float g_partial[CRF_B];
__device__ int   g_count = 0;

typedef unsigned long long u64;

__device__ __forceinline__ float ex2f(float x) {
    float r; asm("ex2.approx.f32 %0, %1;" : "=f"(r) : "f"(x)); return r;
}
__device__ __forceinline__ float lg2f(float x) {
    float r; asm("lg2.approx.f32 %0, %1;" : "=f"(r) : "f"(x)); return r;
}
__device__ __forceinline__ u64 pack2(float lo, float hi) {
    u64 r; asm("mov.b64 %0, {%1, %2};" : "=l"(r) : "f"(lo), "f"(hi)); return r;
}
__device__ __forceinline__ void unpack2(u64 v, float& lo, float& hi) {
    asm("mov.b64 {%0, %1}, %2;" : "=f"(lo), "=f"(hi) : "l"(v));
}
__device__ __forceinline__ u64 ffma2(u64 a, u64 b, u64 c) {
    u64 d; asm("fma.rn.f32x2 %0, %1, %2, %3;" : "=l"(d) : "l"(a), "l"(b), "l"(c));
    return d;
}
__device__ __forceinline__ u64 fadd2(u64 a, u64 b) {
    u64 d; asm("add.rn.f32x2 %0, %1, %2;" : "=l"(d) : "l"(a), "l"(b));
    return d;
}
__device__ __forceinline__ void cp16(uint32_t dst, const void* src) {
    asm volatile("cp.async.cg.shared.global [%0], [%1], 16;" :: "r"(dst), "l"(src));
}

struct RowSmem {                    // per-row (per-warp) staging, ~9 KB
    float sEm[2][CHUNK][CRF_T];     // 8 KB
    float sMk[2][CHUNK];
    int   sTg[2][CHUNK];
    float sE[2][CRF_T];
};

__global__ __launch_bounds__(32 * RPC, 1)
void crf_main(const float* __restrict__ emis,
              const int*   __restrict__ tags,
              const float* __restrict__ mask,
              const float* __restrict__ trans,
              float* __restrict__ out)
{
    const int w  = threadIdx.x >> 5;     // warp = row-within-CTA (one per SMSP)
    const int l  = threadIdx.x & 31;     // lane; owns columns 2l, 2l+1
    const int b  = blockIdx.x * RPC + w;
    const int c0 = 2 * l;

    __shared__ __align__(16) RowSmem row[RPC];   // ~36 KB
    RowSmem& R = row[w];

    const float LOG2E = 1.4426950408889634f;
    const float LN2   = 0.6931471805599453f;

    const float* mb    = mask + (size_t)b * CRF_S;
    const int*   tb    = tags + (size_t)b * CRF_S;
    const float* ebase = emis + (size_t)b * CRF_S * CRF_T;

    // ---- cp.async chunk issuer (chunk c covers steps [16c, 16c+16)) --------
    auto issue_chunk = [&](int c) {
        const int    cb  = c & 1;
        const float* src = ebase + (size_t)c * CHUNK * CRF_T;
        uint32_t d0 = (uint32_t)__cvta_generic_to_shared(&R.sEm[cb][0][0]);
        #pragma unroll
        for (int k = 0; k < 8; k++) {           // 256 sixteen-byte units
            int u = k * 32 + l;
            cp16(d0 + u * 16, src + u * 4);
        }
        if (l < 4) {
            uint32_t dm = (uint32_t)__cvta_generic_to_shared(&R.sMk[cb][0]);
            cp16(dm + l * 16, mb + c * CHUNK + l * 4);
        } else if (l < 8) {
            uint32_t dt = (uint32_t)__cvta_generic_to_shared(&R.sTg[cb][0]);
            cp16(dt + (l - 4) * 16, tb + c * CHUNK + (l - 4) * 4);
        }
        asm volatile("cp.async.commit_group;" ::: "memory");
    };

    issue_chunk(0);
    issue_chunk(1);
    issue_chunk(2);
    issue_chunk(3);

    // -------- Texp columns c0, c0+1 as i-pair-packed f32x2 (64 u64 regs) ----
    u64 tA[CRF_T / 2], tB[CRF_T / 2];
    #pragma unroll
    for (int k = 0; k < CRF_T / 2; k++) {
        float2 r0 = *reinterpret_cast<const float2*>(trans + (2 * k)     * CRF_T + c0);
        float2 r1 = *reinterpret_cast<const float2*>(trans + (2 * k + 1) * CRF_T + c0);
        tA[k] = pack2(ex2f(r0.x * LOG2E), ex2f(r1.x * LOG2E));
        tB[k] = pack2(ex2f(r0.y * LOG2E), ex2f(r1.y * LOG2E));
    }

    // ---------------- init (step 0) ----------------
    float  mk0 = mb[0];
    float2 ev0 = *reinterpret_cast<const float2*>(ebase + c0);
    float s0 = ev0.x * mk0;
    float s1 = ev0.y * mk0;

    // reference chain, all in registers (every lane tracks it redundantly)
    float mref       = __shfl_sync(0xffffffffu, s0, 0);
    float mref_next  = mref;
    float prev_score = mref;

    // gold: step-0 term; rest interleaved into the main loop
    int   tgp = tb[0];
    float g   = ebase[tgp] * mk0;

    // E(1) into buffer 1 (iter s reads sE[s&1])
    *reinterpret_cast<float2*>(&R.sE[1][c0]) =
        make_float2(ex2f((s0 - mref) * LOG2E), ex2f((s1 - mref) * LOG2E));

    // ================= main recurrence =================
    for (int c = 0; c < NCHUNK; ++c) {
        if (c >= NCHUNK - 4) asm volatile("cp.async.wait_group 0;" ::: "memory");
        else                 asm volatile("cp.async.wait_group 3;" ::: "memory");
        __syncwarp();

        const int cb   = c & 1;
        const int sBeg = (c == 0) ? 1 : c * CHUNK;
        const int sEnd = (c == NCHUNK - 1) ? (CRF_S - 1) : (c + 1) * CHUNK;

        #pragma unroll 8
        for (int s = sBeg; s < sEnd; ++s) {
            __syncwarp();                   // orders prev-iter E writes (RAW+WAR)

            const int idx = s & (CHUNK - 1);
            float  mpf = prev_score;        // score_{s-1} (col 0), register
            float2 em  = *reinterpret_cast<const float2*>(&R.sEm[cb][idx][c0]);
            float  mk  = R.sMk[cb][idx];
            float  em0 = R.sEm[cb][idx][0];

            // ---- interleaved gold step (uniform across lanes, off-path) ----
            int   tg  = R.sTg[cb][idx];
            float ge  = R.sEm[cb][idx][tg];
            float gt  = __ldg(trans + tg * CRF_T + tgp);
            g   = fmaf(gt + ge, mk, g);
            tgp = tg;

            // ---- off-critical-path rescale factors (per column) ----
            float mkl   = mk * LOG2E;
            float dref2 = (mref - mref_next) * LOG2E;
            float ed0 = ex2f(fmaf(em.x, mkl, dref2));
            float ed1 = ex2f(fmaf(em.y, mkl, dref2));

            // ---- dot for both columns; E read as pre-packed i-pairs ----
            const ulonglong2* E2 = reinterpret_cast<const ulonglong2*>(R.sE[s & 1]);
            u64 a0 = 0ull, a1 = 0ull, b0 = 0ull, b1 = 0ull;
            #pragma unroll
            for (int k = 0; k < CRF_T / 4; k++) {
                ulonglong2 v = E2[k];
                a0 = ffma2(v.x, tA[2 * k],     a0);
                a1 = ffma2(v.y, tA[2 * k + 1], a1);
                b0 = ffma2(v.x, tB[2 * k],     b0);
                b1 = ffma2(v.y, tB[2 * k + 1], b1);
            }
            u64 ta  = fadd2(a0, a1);
            u64 tb2 = fadd2(b0, b1);
            float xa, ya, xb, yb;
            unpack2(ta, xa, ya); unpack2(tb2, xb, yb);
            float P0 = xa + ya;
            float P1 = xb + yb;

            // E(s+1) in linear space
            *reinterpret_cast<float2*>(&R.sE[(s & 1) ^ 1][c0]) =
                make_float2(P0 * ed0, P1 * ed1);

            // ---- reference score (col 0) computed by ALL lanes: no branch --
            float P0b = __shfl_sync(0xffffffffu, P0, 0);
            prev_score = fmaf(lg2f(P0b), LN2, mref) + em0 * mk;

            mref      = mref_next;
            mref_next = mpf;
        }

        if (c + 4 < NCHUNK) issue_chunk(c + 4);
    }

    // ---------------- peeled last step (s = S-1) ----------------
    {
        const int s   = CRF_S - 1;
        const int cb  = (NCHUNK - 1) & 1;
        const int idx = s & (CHUNK - 1);
        float2 em = *reinterpret_cast<const float2*>(&R.sEm[cb][idx][c0]);
        float  mk = R.sMk[cb][idx];

        int   tg = R.sTg[cb][idx];
        float ge = R.sEm[cb][idx][tg];
        float gt = __ldg(trans + tg * CRF_T + tgp);
        g = fmaf(gt + ge, mk, g);

        __syncwarp();

        const ulonglong2* E2 = reinterpret_cast<const ulonglong2*>(R.sE[s & 1]);
        u64 a0 = 0ull, a1 = 0ull, b0 = 0ull, b1 = 0ull;
        #pragma unroll
        for (int k = 0; k < CRF_T / 4; k++) {
            ulonglong2 v = E2[k];
            a0 = ffma2(v.x, tA[2 * k],     a0);
            a1 = ffma2(v.y, tA[2 * k + 1], a1);
            b0 = ffma2(v.x, tB[2 * k],     b0);
            b1 = ffma2(v.y, tB[2 * k + 1], b1);
        }
        u64 ta  = fadd2(a0, a1);
        u64 tb2 = fadd2(b0, b1);
        float xa, ya, xb, yb;
        unpack2(ta, xa, ya); unpack2(tb2, xb, yb);

        float sc0 = fmaf(lg2f(xa + ya), LN2, mref) + em.x * mk;
        float sc1 = fmaf(lg2f(xb + yb), LN2, mref) + em.y * mk;

        // final logsumexp over 64 states, in-warp
        float m = fmaxf(sc0, sc1);
        #pragma unroll
        for (int off = 16; off; off >>= 1)
            m = fmaxf(m, __shfl_xor_sync(0xffffffffu, m, off));

        float e = ex2f((sc0 - m) * LOG2E) + ex2f((sc1 - m) * LOG2E);
        #pragma unroll
        for (int off = 16; off; off >>= 1)
            e += __shfl_xor_sync(0xffffffffu, e, off);

        if (l == 0) {
            float fwd = fmaf(lg2f(e), LN2, m);
            g_partial[b] = fwd - g;
        }
    }

    // ---------------- last-arriving WARP reduces the mean --------------------
    bool last = false;
    if (l == 0) {
        __threadfence();
        int c = atomicAdd(&g_count, 1);
        last = (c == CRF_B - 1);
        if (last) g_count = 0;              // reset for graph replay
    }
    last = __shfl_sync(0xffffffffu, last, 0);
    if (last) {
        __threadfence();
        float v = 0.f;
        #pragma unroll
        for (int i = 0; i < CRF_B / 32; i++)
            v += g_partial[i * 32 + l];
        #pragma unroll
        for (int off = 16; off; off >>= 1)
            v += __shfl_xor_sync(0xffffffffu, v, off);
        if (l == 0) out[0] = v * (1.0f / CRF_B);
    }
}

extern "C" void kernel_launch(void* const* d_in, const int* in_sizes, int n_in,
                              void* d_out, int out_size)
{
    const float* emis  = (const float*)d_in[0];
    const int*   tags  = (const int*)  d_in[1];
    const float* mask  = (const float*)d_in[2];
    const float* trans = (const float*)d_in[3];

    crf_main<<<NCTA, 32 * RPC>>>(emis, tags, mask, trans, (float*)d_out);
}

// round 11
// speedup vs baseline: 1.8396x; 1.0467x over previous
#include <cuda_runtime.h>
#include <cstdint>

#define CRF_B 512
#define CRF_S 1024
#define CRF_T 64
#define CHUNK 16
#define NCHUNK (CRF_S / CHUNK)     /* 64 */
#define RPC 4                       /* rows (warps) per CTA */
#define NCTA (CRF_B / RPC)          /* 128 */

__device__ float g_partial[CRF_B];
__device__ int   g_count = 0;

typedef unsigned long long u64;

__device__ __forceinline__ float ex2f(float x) {
    float r; asm("ex2.approx.f32 %0, %1;" : "=f"(r) : "f"(x)); return r;
}
__device__ __forceinline__ float lg2f(float x) {
    float r; asm("lg2.approx.f32 %0, %1;" : "=f"(r) : "f"(x)); return r;
}
__device__ __forceinline__ u64 pack2(float lo, float hi) {
    u64 r; asm("mov.b64 %0, {%1, %2};" : "=l"(r) : "f"(lo), "f"(hi)); return r;
}
__device__ __forceinline__ void unpack2(u64 v, float& lo, float& hi) {
    asm("mov.b64 {%0, %1}, %2;" : "=f"(lo), "=f"(hi) : "l"(v));
}
__device__ __forceinline__ u64 ffma2(u64 a, u64 b, u64 c) {
    u64 d; asm("fma.rn.f32x2 %0, %1, %2, %3;" : "=l"(d) : "l"(a), "l"(b), "l"(c));
    return d;
}
__device__ __forceinline__ u64 fadd2(u64 a, u64 b) {
    u64 d; asm("add.rn.f32x2 %0, %1, %2;" : "=l"(d) : "l"(a), "l"(b));
    return d;
}
__device__ __forceinline__ void cp16(uint32_t dst, const void* src) {
    asm volatile("cp.async.cg.shared.global [%0], [%1], 16;" :: "r"(dst), "l"(src));
}

struct RowSmem {                    // per-row (per-warp) staging
    float sEm[2][CHUNK][CRF_T];     // 8 KB
    float sMk[2][CHUNK];
    int   sTg[2][CHUNK];
    float sE[2][CRF_T];
};

__global__ __launch_bounds__(32 * RPC, 1)
void crf_main(const float* __restrict__ emis,
              const int*   __restrict__ tags,
              const float* __restrict__ mask,
              const float* __restrict__ trans,
              float* __restrict__ out)
{
    const int w  = threadIdx.x >> 5;     // warp = row-within-CTA
    const int l  = threadIdx.x & 31;     // lane; owns columns 2l, 2l+1
    const int b  = blockIdx.x * RPC + w;
    const int c0 = 2 * l;

    __shared__ __align__(16) RowSmem row[RPC];
    RowSmem& R = row[w];

    const float LOG2E = 1.4426950408889634f;
    const float LN2   = 0.6931471805599453f;

    const float* mb    = mask + (size_t)b * CRF_S;
    const int*   tb    = tags + (size_t)b * CRF_S;
    const float* ebase = emis + (size_t)b * CRF_S * CRF_T;

    // ---- cp.async chunk issuer (chunk c covers steps [16c, 16c+16)) --------
    auto issue_chunk = [&](int c) {
        const int    cb  = c & 1;
        const float* src = ebase + (size_t)c * CHUNK * CRF_T;
        uint32_t d0 = (uint32_t)__cvta_generic_to_shared(&R.sEm[cb][0][0]);
        #pragma unroll
        for (int k = 0; k < 8; k++) {           // 256 sixteen-byte units
            int u = k * 32 + l;
            cp16(d0 + u * 16, src + u * 4);
        }
        if (l < 4) {
            uint32_t dm = (uint32_t)__cvta_generic_to_shared(&R.sMk[cb][0]);
            cp16(dm + l * 16, mb + c * CHUNK + l * 4);
        } else if (l < 8) {
            uint32_t dt = (uint32_t)__cvta_generic_to_shared(&R.sTg[cb][0]);
            cp16(dt + (l - 4) * 16, tb + c * CHUNK + (l - 4) * 4);
        }
        asm volatile("cp.async.commit_group;" ::: "memory");
    };

    // strictly NBUF=2 chunks in flight: issue c+2 only AFTER consuming chunk c
    issue_chunk(0);
    issue_chunk(1);

    // -------- Texp columns c0, c0+1 as i-pair-packed f32x2 (64 u64 regs) ----
    u64 tA[CRF_T / 2], tB[CRF_T / 2];
    #pragma unroll
    for (int k = 0; k < CRF_T / 2; k++) {
        float2 r0 = *reinterpret_cast<const float2*>(trans + (2 * k)     * CRF_T + c0);
        float2 r1 = *reinterpret_cast<const float2*>(trans + (2 * k + 1) * CRF_T + c0);
        tA[k] = pack2(ex2f(r0.x * LOG2E), ex2f(r1.x * LOG2E));
        tB[k] = pack2(ex2f(r0.y * LOG2E), ex2f(r1.y * LOG2E));
    }

    // ---------------- init (step 0) ----------------
    float  mk0 = mb[0];
    float2 ev0 = *reinterpret_cast<const float2*>(ebase + c0);
    float s0 = ev0.x * mk0;
    float s1 = ev0.y * mk0;

    const float C0 = __shfl_sync(0xffffffffu, s0, 0);   // log-space base offset

    // E(1) = exp(score0 - C0) into buffer 1 (iter s reads sE[s&1])
    *reinterpret_cast<float2*>(&R.sE[1][c0]) =
        make_float2(ex2f((s0 - C0) * LOG2E), ex2f((s1 - C0) * LOG2E));

    // exponent-rescale state (exact power-of-2 normalization, lag 1)
    float dsc   = 1.0f;      // 2^{-uPrev}, applied this iter
    int   uPrev = 0;         // exponent extracted last iter
    int   sexp  = 0;         // sum of APPLIED exponents

    float g = 0.f;           // gold partial (lanes 0..CHUNK-1 accumulate)
    int   tagBound = 0;      // last tag of previous chunk (for lane 0)

    // ================= main recurrence =================
    for (int c = 0; c < NCHUNK; ++c) {
        if (c == NCHUNK - 1) asm volatile("cp.async.wait_group 0;" ::: "memory");
        else                 asm volatile("cp.async.wait_group 1;" ::: "memory");
        __syncwarp();

        const int cb   = c & 1;
        const int sBeg = (c == 0) ? 1 : c * CHUNK;
        const int sEnd = (c == NCHUNK - 1) ? (CRF_S - 1) : (c + 1) * CHUNK;

        // ---- gold prologue: lanes 0..15 each own one step of this chunk ----
        int   tg_c = 0, tg_p = 0;
        float mkc = 0.f, gec = 0.f, gtc = 0.f;
        if (l < CHUNK) {
            tg_c = R.sTg[cb][l];
            tg_p = (l == 0) ? tagBound : R.sTg[cb][l - 1];
            mkc  = R.sMk[cb][l];
            gec  = R.sEm[cb][l][tg_c];
            if (!(c == 0 && l == 0))
                gtc = __ldg(trans + tg_c * CRF_T + tg_p);
        }
        tagBound = R.sTg[cb][CHUNK - 1];     // broadcast; for next chunk's lane 0

        #pragma unroll 8
        for (int s = sBeg; s < sEnd; ++s) {
            __syncwarp();                   // orders prev-iter E writes (RAW+WAR)

            const int idx = s & (CHUNK - 1);
            float2 em = *reinterpret_cast<const float2*>(&R.sEm[cb][idx][c0]);
            float  mk = R.sMk[cb][idx];

            // per-column linear-space multipliers (off the dot's critical path)
            float mkl = mk * LOG2E;
            float ed0 = ex2f(em.x * mkl) * dsc;
            float ed1 = ex2f(em.y * mkl) * dsc;

            // dot: P_j = sum_i E_i * Texp[i][j]; E read as pre-packed i-pairs
            const ulonglong2* E2 = reinterpret_cast<const ulonglong2*>(R.sE[s & 1]);
            u64 a0 = 0ull, a1 = 0ull, b0 = 0ull, b1 = 0ull;
            #pragma unroll
            for (int k = 0; k < CRF_T / 4; k++) {
                ulonglong2 v = E2[k];
                a0 = ffma2(v.x, tA[2 * k],     a0);
                a1 = ffma2(v.y, tA[2 * k + 1], a1);
                b0 = ffma2(v.x, tB[2 * k],     b0);
                b1 = ffma2(v.y, tB[2 * k + 1], b1);
            }
            u64 ta  = fadd2(a0, a1);
            u64 tb2 = fadd2(b0, b1);
            float xa, ya, xb, yb;
            unpack2(ta, xa, ya); unpack2(tb2, xb, yb);
            float P0 = xa + ya;
            float P1 = xb + yb;

            // E(s+1), linear space with lag-1 exact power-of-2 normalization
            *reinterpret_cast<float2*>(&R.sE[(s & 1) ^ 1][c0]) =
                make_float2(P0 * ed0, P1 * ed1);

            // extract exponent of column-0 P for NEXT iter's rescale
            float P0b = __shfl_sync(0xffffffffu, P0, 0);
            sexp += uPrev;                               // account applied u
            int eb = __float_as_int(P0b) >> 23;          // biased exponent
            uPrev = eb - 127;
            dsc   = __int_as_float((254 - eb) << 23);    // 2^{-(eb-127)}
        }

        // gold accumulation (loads long completed; mkc==0 masks idle lanes)
        g = fmaf(gtc + gec, mkc, g);

        if (c + 2 < NCHUNK) issue_chunk(c + 2);
    }

    // ---------------- peeled last step (s = S-1) ----------------
    {
        const int s   = CRF_S - 1;
        const int cb  = (NCHUNK - 1) & 1;
        const int idx = s & (CHUNK - 1);
        float2 em = *reinterpret_cast<const float2*>(&R.sEm[cb][idx][c0]);
        float  mk = R.sMk[cb][idx];

        __syncwarp();

        const ulonglong2* E2 = reinterpret_cast<const ulonglong2*>(R.sE[s & 1]);
        u64 a0 = 0ull, a1 = 0ull, b0 = 0ull, b1 = 0ull;
        #pragma unroll
        for (int k = 0; k < CRF_T / 4; k++) {
            ulonglong2 v = E2[k];
            a0 = ffma2(v.x, tA[2 * k],     a0);
            a1 = ffma2(v.y, tA[2 * k + 1], a1);
            b0 = ffma2(v.x, tB[2 * k],     b0);
            b1 = ffma2(v.y, tB[2 * k + 1], b1);
        }
        u64 ta  = fadd2(a0, a1);
        u64 tb2 = fadd2(b0, b1);
        float xa, ya, xb, yb;
        unpack2(ta, xa, ya); unpack2(tb2, xb, yb);

        // t_j = P_j * exp(em_j * mk): score_j = C + log(t_j)
        float mkl = mk * LOG2E;
        float t0 = (xa + ya) * ex2f(em.x * mkl);
        float t1 = (xb + yb) * ex2f(em.y * mkl);

        // final logsumexp = C + log(sum_j t_j) (t_j positive, well-scaled)
        float tsum = t0 + t1;
        #pragma unroll
        for (int off = 16; off; off >>= 1)
            tsum += __shfl_xor_sync(0xffffffffu, tsum, off);

        // gold: reduce lane partials (lanes >= CHUNK contributed 0)
        #pragma unroll
        for (int off = 16; off; off >>= 1)
            g += __shfl_xor_sync(0xffffffffu, g, off);

        if (l == 0) {
            float C   = fmaf((float)sexp, LN2, C0);
            float fwd = fmaf(lg2f(tsum), LN2, C);
            g_partial[b] = fwd - g;
        }
    }

    // ---------------- last-arriving WARP reduces the mean --------------------
    bool last = false;
    if (l == 0) {
        __threadfence();
        int c = atomicAdd(&g_count, 1);
        last = (c == CRF_B - 1);
        if (last) g_count = 0;              // reset for graph replay
    }
    last = __shfl_sync(0xffffffffu, last, 0);
    if (last) {
        __threadfence();
        float v = 0.f;
        #pragma unroll
        for (int i = 0; i < CRF_B / 32; i++)
            v += g_partial[i * 32 + l];
        #pragma unroll
        for (int off = 16; off; off >>= 1)
            v += __shfl_xor_sync(0xffffffffu, v, off);
        if (l == 0) out[0] = v * (1.0f / CRF_B);
    }
}

extern "C" void kernel_launch(void* const* d_in, const int* in_sizes, int n_in,
                              void* d_out, int out_size)
{
    const float* emis  = (const float*)d_in[0];
    const int*   tags  = (const int*)  d_in[1];
    const float* mask  = (const float*)d_in[2];
    const float* trans = (const float*)d_in[3];

    crf_main<<<NCTA, 32 * RPC>>>(emis, tags, mask, trans, (float*)d_out);
}

// round 12
// speedup vs baseline: 1.9507x; 1.0604x over previous
#include <cuda_runtime.h>
#include <cstdint>

#define CRF_B 512
#define CRF_S 1024
#define CRF_T 64
#define CHUNK 16
#define NCHUNK (CRF_S / CHUNK)     /* 64 */
#define RPC 4                       /* rows (warps) per CTA */
#define NCTA (CRF_B / RPC)          /* 128 */

__device__ float g_partial[CRF_B];
__device__ int   g_count = 0;

typedef unsigned long long u64;

__device__ __forceinline__ float ex2f(float x) {
    float r; asm("ex2.approx.f32 %0, %1;" : "=f"(r) : "f"(x)); return r;
}
__device__ __forceinline__ float lg2f(float x) {
    float r; asm("lg2.approx.f32 %0, %1;" : "=f"(r) : "f"(x)); return r;
}
__device__ __forceinline__ u64 pack2(float lo, float hi) {
    u64 r; asm("mov.b64 %0, {%1, %2};" : "=l"(r) : "f"(lo), "f"(hi)); return r;
}
__device__ __forceinline__ void unpack2(u64 v, float& lo, float& hi) {
    asm("mov.b64 {%0, %1}, %2;" : "=f"(lo), "=f"(hi) : "l"(v));
}
__device__ __forceinline__ u64 ffma2(u64 a, u64 b, u64 c) {
    u64 d; asm("fma.rn.f32x2 %0, %1, %2, %3;" : "=l"(d) : "l"(a), "l"(b), "l"(c));
    return d;
}
__device__ __forceinline__ void cp16(uint32_t dst, const void* src) {
    asm volatile("cp.async.cg.shared.global [%0], [%1], 16;" :: "r"(dst), "l"(src));
}

struct RowSmem {                    // per-row (per-warp) staging
    float sEm[2][CHUNK][CRF_T];     // 8 KB
    float sMk[2][CHUNK];
    int   sTg[2][CHUNK];
    float sE[2][CRF_T];
};

// One recurrence step. PAR (compile-time per unrolled copy) = parity of global
// step s = buffer to read. Rescale: extract exponent at PAR==1, apply (as the
// exact ex2 addend du) at PAR==0.
#define STEP(IDX, CB, PAR) do {                                               \
    __syncwarp();                                                             \
    float2 _em = *reinterpret_cast<const float2*>(&R.sEm[(CB)][(IDX)][c0]);   \
    float  _mk = R.sMk[(CB)][(IDX)];                                          \
    float _mkl = _mk * LOG2E;                                                 \
    float _ed0, _ed1;                                                         \
    if ((PAR) == 0) { _ed0 = ex2f(fmaf(_em.x, _mkl, du));                     \
                      _ed1 = ex2f(fmaf(_em.y, _mkl, du)); }                   \
    else            { _ed0 = ex2f(_em.x * _mkl);                              \
                      _ed1 = ex2f(_em.y * _mkl); }                            \
    const ulonglong2* _E2 = reinterpret_cast<const ulonglong2*>(R.sE[(PAR)]); \
    u64 _a = 0ull, _b = 0ull;                                                 \
    _Pragma("unroll")                                                         \
    for (int _k = 0; _k < 16; _k++) {                                         \
        ulonglong2 _v = _E2[_k];                                              \
        _a = ffma2(_v.x, tA[2 * _k],     _a);                                 \
        _b = ffma2(_v.x, tB[2 * _k],     _b);                                 \
        _a = ffma2(_v.y, tA[2 * _k + 1], _a);                                 \
        _b = ffma2(_v.y, tB[2 * _k + 1], _b);                                 \
    }                                                                         \
    float _xa, _ya, _xb, _yb;                                                 \
    unpack2(_a, _xa, _ya); unpack2(_b, _xb, _yb);                             \
    float _P0 = _xa + _ya, _P1 = _xb + _yb;                                   \
    *reinterpret_cast<float2*>(&R.sE[(PAR) ^ 1][c0]) =                        \
        make_float2(_P0 * _ed0, _P1 * _ed1);                                  \
    if ((PAR) == 1) {                                                         \
        float _P0b = __shfl_sync(0xffffffffu, _P0, 0);                        \
        int _u = (__float_as_int(_P0b) >> 23) - 127;                          \
        sexp += _u;                                                           \
        du = (float)(-_u);                                                    \
    }                                                                         \
} while (0)

// Per-chunk gold prologue: lanes 0..15 each own one step of chunk C.
#define GOLD(CB, C) do {                                                      \
    int   _tgc = 0, _tgp = 0;                                                 \
    float _mkc = 0.f, _gec = 0.f, _gtc = 0.f;                                 \
    if (l < CHUNK) {                                                          \
        _tgc = R.sTg[(CB)][l];                                                \
        _tgp = (l == 0) ? tagBound : R.sTg[(CB)][l - 1];                      \
        _mkc = R.sMk[(CB)][l];                                                \
        _gec = R.sEm[(CB)][l][_tgc];                                          \
        if (!((C) == 0 && l == 0))                                            \
            _gtc = __ldg(trans + _tgc * CRF_T + _tgp);                        \
    }                                                                         \
    tagBound = R.sTg[(CB)][CHUNK - 1];                                        \
    g = fmaf(_gtc + _gec, _mkc, g);                                           \
} while (0)

__global__ __launch_bounds__(32 * RPC, 1)
void crf_main(const float* __restrict__ emis,
              const int*   __restrict__ tags,
              const float* __restrict__ mask,
              const float* __restrict__ trans,
              float* __restrict__ out)
{
    const int w  = threadIdx.x >> 5;     // warp = row-within-CTA
    const int l  = threadIdx.x & 31;     // lane; owns columns 2l, 2l+1
    const int b  = blockIdx.x * RPC + w;
    const int c0 = 2 * l;

    __shared__ __align__(16) RowSmem row[RPC];
    RowSmem& R = row[w];

    const float LOG2E = 1.4426950408889634f;
    const float LN2   = 0.6931471805599453f;

    const float* mb    = mask + (size_t)b * CRF_S;
    const int*   tb    = tags + (size_t)b * CRF_S;
    const float* ebase = emis + (size_t)b * CRF_S * CRF_T;

    // ---- cp.async chunk issuer (chunk c covers steps [16c, 16c+16)) --------
    auto issue_chunk = [&](int c) {
        const int    cb  = c & 1;
        const float* src = ebase + (size_t)c * CHUNK * CRF_T;
        uint32_t d0 = (uint32_t)__cvta_generic_to_shared(&R.sEm[cb][0][0]);
        #pragma unroll
        for (int k = 0; k < 8; k++) {           // 256 sixteen-byte units
            int u = k * 32 + l;
            cp16(d0 + u * 16, src + u * 4);
        }
        if (l < 4) {
            uint32_t dm = (uint32_t)__cvta_generic_to_shared(&R.sMk[cb][0]);
            cp16(dm + l * 16, mb + c * CHUNK + l * 4);
        } else if (l < 8) {
            uint32_t dt = (uint32_t)__cvta_generic_to_shared(&R.sTg[cb][0]);
            cp16(dt + (l - 4) * 16, tb + c * CHUNK + (l - 4) * 4);
        }
        asm volatile("cp.async.commit_group;" ::: "memory");
    };

    // strictly 2 chunks in flight
    issue_chunk(0);
    issue_chunk(1);

    // -------- Texp columns c0, c0+1 as i-pair-packed f32x2 (64 u64 regs) ----
    u64 tA[CRF_T / 2], tB[CRF_T / 2];
    #pragma unroll
    for (int k = 0; k < CRF_T / 2; k++) {
        float2 r0 = *reinterpret_cast<const float2*>(trans + (2 * k)     * CRF_T + c0);
        float2 r1 = *reinterpret_cast<const float2*>(trans + (2 * k + 1) * CRF_T + c0);
        tA[k] = pack2(ex2f(r0.x * LOG2E), ex2f(r1.x * LOG2E));
        tB[k] = pack2(ex2f(r0.y * LOG2E), ex2f(r1.y * LOG2E));
    }

    // ---------------- init (step 0) ----------------
    float  mk0 = mb[0];
    float2 ev0 = *reinterpret_cast<const float2*>(ebase + c0);
    float s0 = ev0.x * mk0;
    float s1 = ev0.y * mk0;

    const float C0 = __shfl_sync(0xffffffffu, s0, 0);   // log-space base offset

    // E(1) = exp(score0 - C0) into buffer 1 (iter s reads sE[s&1])
    *reinterpret_cast<float2*>(&R.sE[1][c0]) =
        make_float2(ex2f((s0 - C0) * LOG2E), ex2f((s1 - C0) * LOG2E));

    float du   = 0.f;        // exact power-of-2 log2-addend, applied at even s
    int   sexp = 0;          // sum of applied exponents
    float g    = 0.f;        // gold partials (lanes 0..15)
    int   tagBound = 0;

    // ---------------- chunk 0 peeled: steps s = 1..15 ----------------
    {
        asm volatile("cp.async.wait_group 1;" ::: "memory");
        __syncwarp();
        GOLD(0, 0);
        #pragma unroll 4
        for (int k = 1; k < 16; k++)
            STEP(k, 0, (k & 1));
        issue_chunk(2);
    }

    // ---------------- chunks 1..62: 16 steps each ----------------
    for (int c = 1; c < NCHUNK - 1; ++c) {
        asm volatile("cp.async.wait_group 1;" ::: "memory");
        __syncwarp();
        const int cb = c & 1;
        GOLD(cb, c);
        #pragma unroll 4
        for (int k = 0; k < 16; k++)
            STEP(k, cb, (k & 1));          // s = 16c+k, parity = k&1
        if (c + 2 < NCHUNK) issue_chunk(c + 2);
    }

    // ---------------- chunk 63: steps s = 1008..1022 ----------------
    {
        asm volatile("cp.async.wait_group 0;" ::: "memory");
        __syncwarp();
        GOLD(1, NCHUNK - 1);               // cb = 63 & 1 = 1
        #pragma unroll 4
        for (int k = 0; k < 15; k++)
            STEP(k, 1, (k & 1));
    }

    // ---------------- peeled last step (s = 1023, reads buf 1) --------------
    {
        float2 em = *reinterpret_cast<const float2*>(&R.sEm[1][15][c0]);
        float  mk = R.sMk[1][15];

        __syncwarp();

        const ulonglong2* E2 = reinterpret_cast<const ulonglong2*>(R.sE[1]);
        u64 a = 0ull, bb = 0ull;
        #pragma unroll
        for (int k = 0; k < 16; k++) {
            ulonglong2 v = E2[k];
            a  = ffma2(v.x, tA[2 * k],     a);
            bb = ffma2(v.x, tB[2 * k],     bb);
            a  = ffma2(v.y, tA[2 * k + 1], a);
            bb = ffma2(v.y, tB[2 * k + 1], bb);
        }
        float xa, ya, xb, yb;
        unpack2(a, xa, ya); unpack2(bb, xb, yb);

        // t_j = P_j * exp(em_j * mk); score_j = C + log(t_j)
        float mkl = mk * LOG2E;
        float t0 = (xa + ya) * ex2f(em.x * mkl);
        float t1 = (xb + yb) * ex2f(em.y * mkl);

        float tsum = t0 + t1;
        #pragma unroll
        for (int off = 16; off; off >>= 1)
            tsum += __shfl_xor_sync(0xffffffffu, tsum, off);

        // gold: reduce lane partials
        #pragma unroll
        for (int off = 16; off; off >>= 1)
            g += __shfl_xor_sync(0xffffffffu, g, off);

        if (l == 0) {
            float C   = fmaf((float)sexp, LN2, C0);
            float fwd = fmaf(lg2f(tsum), LN2, C);
            g_partial[b] = fwd - g;
        }
    }

    // ---------------- last-arriving WARP reduces the mean --------------------
    bool last = false;
    if (l == 0) {
        __threadfence();
        int c = atomicAdd(&g_count, 1);
        last = (c == CRF_B - 1);
        if (last) g_count = 0;              // reset for graph replay
    }
    last = __shfl_sync(0xffffffffu, last, 0);
    if (last) {
        __threadfence();
        float v = 0.f;
        #pragma unroll
        for (int i = 0; i < CRF_B / 32; i++)
            v += g_partial[i * 32 + l];
        #pragma unroll
        for (int off = 16; off; off >>= 1)
            v += __shfl_xor_sync(0xffffffffu, v, off);
        if (l == 0) out[0] = v * (1.0f / CRF_B);
    }
}

extern "C" void kernel_launch(void* const* d_in, const int* in_sizes, int n_in,
                              void* d_out, int out_size)
{
    const float* emis  = (const float*)d_in[0];
    const int*   tags  = (const int*)  d_in[1];
    const float* mask  = (const float*)d_in[2];
    const float* trans = (const float*)d_in[3];

    crf_main<<<NCTA, 32 * RPC>>>(emis, tags, mask, trans, (float*)d_out);
}